// round 1
// baseline (speedup 1.0000x reference)
#include <cuda_runtime.h>
#include <math.h>

#define NPTS 8192
#define DIM  128

// ---------------- device scratch (no allocations allowed) ----------------
__device__ float         g_dist[(size_t)NPTS * NPTS];  // 256 MB distance matrix
__device__ float         g_sq[NPTS];
__device__ unsigned char g_lab[NPTS];
__device__ float         g_loss[NPTS];
__device__ float         g_accv[NPTS];
__device__ float         g_tpv[NPTS];
__device__ float         g_tnv[NPTS];
__device__ int           g_is32;

// ---------------- dtype detection for targets (int32 vs int64) -----------
// Labels are uniform in [0,128). If targets are int64 little-endian, every odd
// int32 slot (high word) is 0. If int32, odd slots are real labels and the OR
// over 4096 of them is nonzero with overwhelming certainty. Only reads the
// first 8192 int32 slots = 32KB, safe for either layout.
__global__ void detect_kernel(const int* __restrict__ t) {
    int local = 0;
    for (int j = threadIdx.x; j < 4096; j += blockDim.x) local |= t[2 * j + 1];
#pragma unroll
    for (int off = 16; off; off >>= 1) local |= __shfl_down_sync(0xffffffffu, local, off);
    __shared__ int s[8];
    if ((threadIdx.x & 31) == 0) s[threadIdx.x >> 5] = local;
    __syncthreads();
    if (threadIdx.x == 0) {
        int f = 0;
        for (int w = 0; w < 8; w++) f |= s[w];
        g_is32 = (f != 0);
    }
}

__global__ void conv_kernel(const void* __restrict__ t) {
    int is32 = g_is32;
    int i = blockIdx.x * blockDim.x + threadIdx.x;
    if (i < NPTS) {
        int v = is32 ? ((const int*)t)[i] : (int)(((const long long*)t)[i]);
        g_lab[i] = (unsigned char)v;
    }
}

// ---------------- squared norms ----------------
__global__ void sq_kernel(const float* __restrict__ X) {
    int i = blockIdx.x;
    int tid = threadIdx.x;  // 128 threads
    float v = X[i * DIM + tid];
    v *= v;
#pragma unroll
    for (int off = 16; off; off >>= 1) v += __shfl_down_sync(0xffffffffu, v, off);
    __shared__ float s[4];
    if ((tid & 31) == 0) s[tid >> 5] = v;
    __syncthreads();
    if (tid == 0) g_sq[i] = s[0] + s[1] + s[2] + s[3];
}

// ---------------- distance matrix: tiled fp32 "GEMM" ----------------
// 128x128 tile per block, 256 threads, 8x8 micro-tile per thread, BK=16.
__global__ void __launch_bounds__(256) dist_kernel(const float* __restrict__ X) {
    __shared__ float As[16][128];
    __shared__ float Bs[16][128];

    const int bx = blockIdx.x;  // column tile (j)
    const int by = blockIdx.y;  // row tile (i)
    const int tid = threadIdx.x;
    const int tx = tid & 15;
    const int ty = tid >> 4;
    const int rowbase = by * 128;
    const int colbase = bx * 128;

    float acc[8][8];
#pragma unroll
    for (int a = 0; a < 8; a++)
#pragma unroll
        for (int b = 0; b < 8; b++) acc[a][b] = 0.0f;

    for (int k0 = 0; k0 < DIM; k0 += 16) {
#pragma unroll
        for (int r = 0; r < 2; r++) {
            int pos = tid + r * 256;     // 0..511
            int row = pos >> 2;          // 0..127
            int kc  = pos & 3;           // 0..3 (float4 chunk within the 16 k's)
            float4 va = *(const float4*)&X[(size_t)(rowbase + row) * DIM + k0 + kc * 4];
            As[kc * 4 + 0][row] = va.x;
            As[kc * 4 + 1][row] = va.y;
            As[kc * 4 + 2][row] = va.z;
            As[kc * 4 + 3][row] = va.w;
            float4 vb = *(const float4*)&X[(size_t)(colbase + row) * DIM + k0 + kc * 4];
            Bs[kc * 4 + 0][row] = vb.x;
            Bs[kc * 4 + 1][row] = vb.y;
            Bs[kc * 4 + 2][row] = vb.z;
            Bs[kc * 4 + 3][row] = vb.w;
        }
        __syncthreads();
#pragma unroll
        for (int kk = 0; kk < 16; kk++) {
            float ar[8], br[8];
            *(float4*)&ar[0] = *(const float4*)&As[kk][ty * 8];
            *(float4*)&ar[4] = *(const float4*)&As[kk][ty * 8 + 4];
            *(float4*)&br[0] = *(const float4*)&Bs[kk][tx * 8];
            *(float4*)&br[4] = *(const float4*)&Bs[kk][tx * 8 + 4];
#pragma unroll
            for (int a = 0; a < 8; a++)
#pragma unroll
                for (int b = 0; b < 8; b++) acc[a][b] = fmaf(ar[a], br[b], acc[a][b]);
        }
        __syncthreads();
    }

    float sqa[8], sqb[8];
#pragma unroll
    for (int a = 0; a < 8; a++) sqa[a] = g_sq[rowbase + ty * 8 + a];
#pragma unroll
    for (int b = 0; b < 8; b++) sqb[b] = g_sq[colbase + tx * 8 + b];

#pragma unroll
    for (int a = 0; a < 8; a++) {
        int row = rowbase + ty * 8 + a;
        float4 o0, o1;
        o0.x = sqrtf(fmaxf(sqa[a] + sqb[0] - 2.0f * acc[a][0], 1e-12f));
        o0.y = sqrtf(fmaxf(sqa[a] + sqb[1] - 2.0f * acc[a][1], 1e-12f));
        o0.z = sqrtf(fmaxf(sqa[a] + sqb[2] - 2.0f * acc[a][2], 1e-12f));
        o0.w = sqrtf(fmaxf(sqa[a] + sqb[3] - 2.0f * acc[a][3], 1e-12f));
        o1.x = sqrtf(fmaxf(sqa[a] + sqb[4] - 2.0f * acc[a][4], 1e-12f));
        o1.y = sqrtf(fmaxf(sqa[a] + sqb[5] - 2.0f * acc[a][5], 1e-12f));
        o1.z = sqrtf(fmaxf(sqa[a] + sqb[6] - 2.0f * acc[a][6], 1e-12f));
        o1.w = sqrtf(fmaxf(sqa[a] + sqb[7] - 2.0f * acc[a][7], 1e-12f));
        *(float4*)&g_dist[(size_t)row * NPTS + colbase + tx * 8]     = o0;
        *(float4*)&g_dist[(size_t)row * NPTS + colbase + tx * 8 + 4] = o1;
    }
}

// ---------------- per-row: threshold (17th smallest) + masked sums --------
__global__ void __launch_bounds__(256) row_kernel() {
    const int i = blockIdx.x;
    const int tid = threadIdx.x;
    const int lane = tid & 31;
    const int wid = tid >> 5;
    const float INF = __int_as_float(0x7f800000);

    __shared__ float srow[NPTS];           // 32 KB
    __shared__ unsigned char slab[NPTS];   // 8 KB
    __shared__ float rv[8];
    __shared__ int ri[8];
    __shared__ float selv[17];
    __shared__ int seli[17];
    __shared__ float sps[8], sns[8];
    __shared__ int scp[8], scn[8], sfp[8], san[8];

    const float* drow = g_dist + (size_t)i * NPTS;
    for (int j = tid; j < NPTS; j += 256) {
        srow[j] = (j == i) ? INF : drow[j];
        slab[j] = g_lab[j];
    }
    __syncthreads();

    // extract the 17 smallest (0-based index 16 of the sorted row = threshold)
    for (int t = 0; t < 17; t++) {
        float mv = INF;
        int mi = NPTS;
        for (int j = tid; j < NPTS; j += 256) {
            float v = srow[j];
            if (v < mv) { mv = v; mi = j; }
        }
#pragma unroll
        for (int off = 16; off; off >>= 1) {
            float ov = __shfl_down_sync(0xffffffffu, mv, off);
            int   oi = __shfl_down_sync(0xffffffffu, mi, off);
            if (ov < mv || (ov == mv && oi < mi)) { mv = ov; mi = oi; }
        }
        if (lane == 0) { rv[wid] = mv; ri[wid] = mi; }
        __syncthreads();
        if (tid == 0) {
            float bv = rv[0]; int bi = ri[0];
            for (int w = 1; w < 8; w++)
                if (rv[w] < bv || (rv[w] == bv && ri[w] < bi)) { bv = rv[w]; bi = ri[w]; }
            selv[t] = bv; seli[t] = bi;
            srow[bi] = INF;  // remove so next extraction finds the next one
        }
        __syncthreads();
    }
    // restore the extracted values (the sums need them)
    if (tid < 17) srow[seli[tid]] = selv[tid];
    __syncthreads();

    const float thr = selv[16];
    const int myl = slab[i];

    float ps = 0.0f, ns = 0.0f;
    int cp = 0, cn = 0, fp = NPTS, anyneg = 0;
    for (int j = tid; j < NPTS; j += 256) {
        if (j == i) continue;
        float dv = srow[j];
        bool below = dv < thr;
        if (slab[j] == myl) {
            if (j < fp) fp = j;
            if (below) { ps += expf(-dv); cp++; }
        } else {
            anyneg = 1;
            if (below) { ns += expf(-dv); cn++; }
        }
    }
#pragma unroll
    for (int off = 16; off; off >>= 1) {
        ps += __shfl_down_sync(0xffffffffu, ps, off);
        ns += __shfl_down_sync(0xffffffffu, ns, off);
        cp += __shfl_down_sync(0xffffffffu, cp, off);
        cn += __shfl_down_sync(0xffffffffu, cn, off);
        int ofp = __shfl_down_sync(0xffffffffu, fp, off);
        fp = min(fp, ofp);
        anyneg |= __shfl_down_sync(0xffffffffu, anyneg, off);
    }
    if (lane == 0) { sps[wid] = ps; sns[wid] = ns; scp[wid] = cp; scn[wid] = cn; sfp[wid] = fp; san[wid] = anyneg; }
    __syncthreads();
    if (tid == 0) {
        ps = 0; ns = 0; cp = 0; cn = 0; fp = NPTS; anyneg = 0;
        for (int w = 0; w < 8; w++) {
            ps += sps[w]; ns += sns[w]; cp += scp[w]; cn += scn[w];
            fp = min(fp, sfp[w]); anyneg |= san[w];
        }
        bool haspos = (fp < NPTS);
        bool validr = haspos && (anyneg != 0);
        float pos_eff = (cp == 0) ? (haspos ? expf(-srow[fp]) : 1.0f) : ps;
        float loss_i = validr ? logf((pos_eff + ns) / pos_eff) : 0.0f;
        int cpa = (cp == 0) ? 1 : cp;
        g_loss[i] = loss_i;
        g_accv[i] = (validr && cpa > cn) ? 1.0f : 0.0f;
        g_tpv[i]  = validr ? (float)cp : 0.0f;
        g_tnv[i]  = validr ? (float)cn : 0.0f;
    }
}

// ---------------- deterministic final reduction ----------------
__global__ void finalize_kernel(float* __restrict__ out) {
    __shared__ float s0[256], s1[256], s2[256], s3[256];
    int tid = threadIdx.x;
    float a = 0, b = 0, c = 0, d = 0;
    for (int j = tid; j < NPTS; j += 256) {
        a += g_loss[j]; b += g_accv[j]; c += g_tpv[j]; d += g_tnv[j];
    }
    s0[tid] = a; s1[tid] = b; s2[tid] = c; s3[tid] = d;
    __syncthreads();
    for (int off = 128; off; off >>= 1) {
        if (tid < off) {
            s0[tid] += s0[tid + off];
            s1[tid] += s1[tid + off];
            s2[tid] += s2[tid + off];
            s3[tid] += s3[tid + off];
        }
        __syncthreads();
    }
    if (tid == 0) {
        const float inv = 1.0f / (float)NPTS;
        out[0] = s0[0] * inv;  // loss
        out[1] = s1[0] * inv;  // accuracy
        out[2] = s2[0] * inv;  // tp
        out[3] = s3[0] * inv;  // tn
    }
}

extern "C" void kernel_launch(void* const* d_in, const int* in_sizes, int n_in,
                              void* d_out, int out_size) {
    const float* X = (const float*)d_in[0];
    const void* T = d_in[1];
    float* out = (float*)d_out;
    (void)in_sizes; (void)n_in; (void)out_size;

    detect_kernel<<<1, 256>>>((const int*)T);
    conv_kernel<<<(NPTS + 255) / 256, 256>>>(T);
    sq_kernel<<<NPTS, 128>>>(X);
    dim3 grid(NPTS / 128, NPTS / 128);
    dist_kernel<<<grid, 256>>>(X);
    row_kernel<<<NPTS, 256>>>();
    finalize_kernel<<<1, 256>>>(out);
}

// round 2
// speedup vs baseline: 1.0005x; 1.0005x over previous
#include <cuda_runtime.h>
#include <math.h>

#define NPTS 8192
#define DIM  128

// ---------------- device scratch (no allocations allowed) ----------------
__device__ float         g_dist[(size_t)NPTS * NPTS];  // 256 MB distance matrix
__device__ float         g_sq[NPTS];
__device__ unsigned char g_lab[NPTS];
__device__ float         g_loss[NPTS];
__device__ float         g_accv[NPTS];
__device__ float         g_tpv[NPTS];
__device__ float         g_tnv[NPTS];
__device__ int           g_is32;

// ---------------- dtype detection for targets (int32 vs int64) -----------
// Labels are uniform in [0,128). If targets are int64 little-endian, every odd
// int32 slot (high word) is 0. If int32, odd slots are real labels and the OR
// over 4096 of them is nonzero with overwhelming certainty. Only reads the
// first 8192 int32 slots = 32KB, safe for either layout.
__global__ void detect_kernel(const int* __restrict__ t) {
    int local = 0;
    for (int j = threadIdx.x; j < 4096; j += blockDim.x) local |= t[2 * j + 1];
#pragma unroll
    for (int off = 16; off; off >>= 1) local |= __shfl_down_sync(0xffffffffu, local, off);
    __shared__ int s[8];
    if ((threadIdx.x & 31) == 0) s[threadIdx.x >> 5] = local;
    __syncthreads();
    if (threadIdx.x == 0) {
        int f = 0;
        for (int w = 0; w < 8; w++) f |= s[w];
        g_is32 = (f != 0);
    }
}

__global__ void conv_kernel(const void* __restrict__ t) {
    int is32 = g_is32;
    int i = blockIdx.x * blockDim.x + threadIdx.x;
    if (i < NPTS) {
        int v = is32 ? ((const int*)t)[i] : (int)(((const long long*)t)[i]);
        g_lab[i] = (unsigned char)v;
    }
}

// ---------------- squared norms ----------------
__global__ void sq_kernel(const float* __restrict__ X) {
    int i = blockIdx.x;
    int tid = threadIdx.x;  // 128 threads
    float v = X[i * DIM + tid];
    v *= v;
#pragma unroll
    for (int off = 16; off; off >>= 1) v += __shfl_down_sync(0xffffffffu, v, off);
    __shared__ float s[4];
    if ((tid & 31) == 0) s[tid >> 5] = v;
    __syncthreads();
    if (tid == 0) g_sq[i] = s[0] + s[1] + s[2] + s[3];
}

// ---------------- distance matrix: tiled fp32 "GEMM" ----------------
// 128x128 tile per block, 256 threads, 8x8 micro-tile per thread, BK=16.
__global__ void __launch_bounds__(256) dist_kernel(const float* __restrict__ X) {
    __shared__ float As[16][128];
    __shared__ float Bs[16][128];

    const int bx = blockIdx.x;  // column tile (j)
    const int by = blockIdx.y;  // row tile (i)
    const int tid = threadIdx.x;
    const int tx = tid & 15;
    const int ty = tid >> 4;
    const int rowbase = by * 128;
    const int colbase = bx * 128;

    float acc[8][8];
#pragma unroll
    for (int a = 0; a < 8; a++)
#pragma unroll
        for (int b = 0; b < 8; b++) acc[a][b] = 0.0f;

    for (int k0 = 0; k0 < DIM; k0 += 16) {
#pragma unroll
        for (int r = 0; r < 2; r++) {
            int pos = tid + r * 256;     // 0..511
            int row = pos >> 2;          // 0..127
            int kc  = pos & 3;           // 0..3 (float4 chunk within the 16 k's)
            float4 va = *(const float4*)&X[(size_t)(rowbase + row) * DIM + k0 + kc * 4];
            As[kc * 4 + 0][row] = va.x;
            As[kc * 4 + 1][row] = va.y;
            As[kc * 4 + 2][row] = va.z;
            As[kc * 4 + 3][row] = va.w;
            float4 vb = *(const float4*)&X[(size_t)(colbase + row) * DIM + k0 + kc * 4];
            Bs[kc * 4 + 0][row] = vb.x;
            Bs[kc * 4 + 1][row] = vb.y;
            Bs[kc * 4 + 2][row] = vb.z;
            Bs[kc * 4 + 3][row] = vb.w;
        }
        __syncthreads();
#pragma unroll
        for (int kk = 0; kk < 16; kk++) {
            float ar[8], br[8];
            *(float4*)&ar[0] = *(const float4*)&As[kk][ty * 8];
            *(float4*)&ar[4] = *(const float4*)&As[kk][ty * 8 + 4];
            *(float4*)&br[0] = *(const float4*)&Bs[kk][tx * 8];
            *(float4*)&br[4] = *(const float4*)&Bs[kk][tx * 8 + 4];
#pragma unroll
            for (int a = 0; a < 8; a++)
#pragma unroll
                for (int b = 0; b < 8; b++) acc[a][b] = fmaf(ar[a], br[b], acc[a][b]);
        }
        __syncthreads();
    }

    float sqa[8], sqb[8];
#pragma unroll
    for (int a = 0; a < 8; a++) sqa[a] = g_sq[rowbase + ty * 8 + a];
#pragma unroll
    for (int b = 0; b < 8; b++) sqb[b] = g_sq[colbase + tx * 8 + b];

#pragma unroll
    for (int a = 0; a < 8; a++) {
        int row = rowbase + ty * 8 + a;
        float4 o0, o1;
        o0.x = sqrtf(fmaxf(sqa[a] + sqb[0] - 2.0f * acc[a][0], 1e-12f));
        o0.y = sqrtf(fmaxf(sqa[a] + sqb[1] - 2.0f * acc[a][1], 1e-12f));
        o0.z = sqrtf(fmaxf(sqa[a] + sqb[2] - 2.0f * acc[a][2], 1e-12f));
        o0.w = sqrtf(fmaxf(sqa[a] + sqb[3] - 2.0f * acc[a][3], 1e-12f));
        o1.x = sqrtf(fmaxf(sqa[a] + sqb[4] - 2.0f * acc[a][4], 1e-12f));
        o1.y = sqrtf(fmaxf(sqa[a] + sqb[5] - 2.0f * acc[a][5], 1e-12f));
        o1.z = sqrtf(fmaxf(sqa[a] + sqb[6] - 2.0f * acc[a][6], 1e-12f));
        o1.w = sqrtf(fmaxf(sqa[a] + sqb[7] - 2.0f * acc[a][7], 1e-12f));
        *(float4*)&g_dist[(size_t)row * NPTS + colbase + tx * 8]     = o0;
        *(float4*)&g_dist[(size_t)row * NPTS + colbase + tx * 8 + 4] = o1;
    }
}

// ---------------- per-row: threshold (17th smallest) + masked sums --------
__global__ void __launch_bounds__(256) row_kernel() {
    const int i = blockIdx.x;
    const int tid = threadIdx.x;
    const int lane = tid & 31;
    const int wid = tid >> 5;
    const float INF = __int_as_float(0x7f800000);

    __shared__ float srow[NPTS];           // 32 KB
    __shared__ unsigned char slab[NPTS];   // 8 KB
    __shared__ float rv[8];
    __shared__ int ri[8];
    __shared__ float selv[17];
    __shared__ int seli[17];
    __shared__ float sps[8], sns[8];
    __shared__ int scp[8], scn[8], sfp[8], san[8];

    const float* drow = g_dist + (size_t)i * NPTS;
    for (int j = tid; j < NPTS; j += 256) {
        srow[j] = (j == i) ? INF : drow[j];
        slab[j] = g_lab[j];
    }
    __syncthreads();

    // extract the 17 smallest (0-based index 16 of the sorted row = threshold)
    for (int t = 0; t < 17; t++) {
        float mv = INF;
        int mi = NPTS;
        for (int j = tid; j < NPTS; j += 256) {
            float v = srow[j];
            if (v < mv) { mv = v; mi = j; }
        }
#pragma unroll
        for (int off = 16; off; off >>= 1) {
            float ov = __shfl_down_sync(0xffffffffu, mv, off);
            int   oi = __shfl_down_sync(0xffffffffu, mi, off);
            if (ov < mv || (ov == mv && oi < mi)) { mv = ov; mi = oi; }
        }
        if (lane == 0) { rv[wid] = mv; ri[wid] = mi; }
        __syncthreads();
        if (tid == 0) {
            float bv = rv[0]; int bi = ri[0];
            for (int w = 1; w < 8; w++)
                if (rv[w] < bv || (rv[w] == bv && ri[w] < bi)) { bv = rv[w]; bi = ri[w]; }
            selv[t] = bv; seli[t] = bi;
            srow[bi] = INF;  // remove so next extraction finds the next one
        }
        __syncthreads();
    }
    // restore the extracted values (the sums need them)
    if (tid < 17) srow[seli[tid]] = selv[tid];
    __syncthreads();

    const float thr = selv[16];
    const int myl = slab[i];

    float ps = 0.0f, ns = 0.0f;
    int cp = 0, cn = 0, fp = NPTS, anyneg = 0;
    for (int j = tid; j < NPTS; j += 256) {
        if (j == i) continue;
        float dv = srow[j];
        bool below = dv < thr;
        if (slab[j] == myl) {
            if (j < fp) fp = j;
            if (below) { ps += expf(-dv); cp++; }
        } else {
            anyneg = 1;
            if (below) { ns += expf(-dv); cn++; }
        }
    }
#pragma unroll
    for (int off = 16; off; off >>= 1) {
        ps += __shfl_down_sync(0xffffffffu, ps, off);
        ns += __shfl_down_sync(0xffffffffu, ns, off);
        cp += __shfl_down_sync(0xffffffffu, cp, off);
        cn += __shfl_down_sync(0xffffffffu, cn, off);
        int ofp = __shfl_down_sync(0xffffffffu, fp, off);
        fp = min(fp, ofp);
        anyneg |= __shfl_down_sync(0xffffffffu, anyneg, off);
    }
    if (lane == 0) { sps[wid] = ps; sns[wid] = ns; scp[wid] = cp; scn[wid] = cn; sfp[wid] = fp; san[wid] = anyneg; }
    __syncthreads();
    if (tid == 0) {
        ps = 0; ns = 0; cp = 0; cn = 0; fp = NPTS; anyneg = 0;
        for (int w = 0; w < 8; w++) {
            ps += sps[w]; ns += sns[w]; cp += scp[w]; cn += scn[w];
            fp = min(fp, sfp[w]); anyneg |= san[w];
        }
        bool haspos = (fp < NPTS);
        bool validr = haspos && (anyneg != 0);
        float pos_eff = (cp == 0) ? (haspos ? expf(-srow[fp]) : 1.0f) : ps;
        float loss_i = validr ? logf((pos_eff + ns) / pos_eff) : 0.0f;
        int cpa = (cp == 0) ? 1 : cp;
        g_loss[i] = loss_i;
        g_accv[i] = (validr && cpa > cn) ? 1.0f : 0.0f;
        g_tpv[i]  = validr ? (float)cp : 0.0f;
        g_tnv[i]  = validr ? (float)cn : 0.0f;
    }
}

// ---------------- deterministic final reduction ----------------
__global__ void finalize_kernel(float* __restrict__ out) {
    __shared__ float s0[256], s1[256], s2[256], s3[256];
    int tid = threadIdx.x;
    float a = 0, b = 0, c = 0, d = 0;
    for (int j = tid; j < NPTS; j += 256) {
        a += g_loss[j]; b += g_accv[j]; c += g_tpv[j]; d += g_tnv[j];
    }
    s0[tid] = a; s1[tid] = b; s2[tid] = c; s3[tid] = d;
    __syncthreads();
    for (int off = 128; off; off >>= 1) {
        if (tid < off) {
            s0[tid] += s0[tid + off];
            s1[tid] += s1[tid + off];
            s2[tid] += s2[tid + off];
            s3[tid] += s3[tid + off];
        }
        __syncthreads();
    }
    if (tid == 0) {
        const float inv = 1.0f / (float)NPTS;
        out[0] = s0[0] * inv;  // loss
        out[1] = s1[0] * inv;  // accuracy
        out[2] = s2[0] * inv;  // tp
        out[3] = s3[0] * inv;  // tn
    }
}

extern "C" void kernel_launch(void* const* d_in, const int* in_sizes, int n_in,
                              void* d_out, int out_size) {
    const float* X = (const float*)d_in[0];
    const void* T = d_in[1];
    float* out = (float*)d_out;
    (void)in_sizes; (void)n_in; (void)out_size;

    detect_kernel<<<1, 256>>>((const int*)T);
    conv_kernel<<<(NPTS + 255) / 256, 256>>>(T);
    sq_kernel<<<NPTS, 128>>>(X);
    dim3 grid(NPTS / 128, NPTS / 128);
    dist_kernel<<<grid, 256>>>(X);
    row_kernel<<<NPTS, 256>>>();
    finalize_kernel<<<1, 256>>>(out);
}

// round 3
// speedup vs baseline: 1.0023x; 1.0018x over previous
#include <cuda_runtime.h>
#include <math.h>

#define NPTS 8192
#define DIM  128

// ---------------- device scratch (no allocations allowed) ----------------
__device__ float         g_dist[(size_t)NPTS * NPTS];  // 256 MB distance matrix
__device__ float         g_sq[NPTS];
__device__ unsigned char g_lab[NPTS];
__device__ float         g_loss[NPTS];
__device__ float         g_accv[NPTS];
__device__ float         g_tpv[NPTS];
__device__ float         g_tnv[NPTS];
__device__ int           g_is32;

// ---------------- dtype detection for targets (int32 vs int64) -----------
// Labels are uniform in [0,128). If targets are int64 little-endian, every odd
// int32 slot (high word) is 0. If int32, odd slots are real labels and the OR
// over 4096 of them is nonzero with overwhelming certainty. Only reads the
// first 8192 int32 slots = 32KB, safe for either layout.
__global__ void detect_kernel(const int* __restrict__ t) {
    int local = 0;
    for (int j = threadIdx.x; j < 4096; j += blockDim.x) local |= t[2 * j + 1];
#pragma unroll
    for (int off = 16; off; off >>= 1) local |= __shfl_down_sync(0xffffffffu, local, off);
    __shared__ int s[8];
    if ((threadIdx.x & 31) == 0) s[threadIdx.x >> 5] = local;
    __syncthreads();
    if (threadIdx.x == 0) {
        int f = 0;
        for (int w = 0; w < 8; w++) f |= s[w];
        g_is32 = (f != 0);
    }
}

__global__ void conv_kernel(const void* __restrict__ t) {
    int is32 = g_is32;
    int i = blockIdx.x * blockDim.x + threadIdx.x;
    if (i < NPTS) {
        int v = is32 ? ((const int*)t)[i] : (int)(((const long long*)t)[i]);
        g_lab[i] = (unsigned char)v;
    }
}

// ---------------- squared norms ----------------
__global__ void sq_kernel(const float* __restrict__ X) {
    int i = blockIdx.x;
    int tid = threadIdx.x;  // 128 threads
    float v = X[i * DIM + tid];
    v *= v;
#pragma unroll
    for (int off = 16; off; off >>= 1) v += __shfl_down_sync(0xffffffffu, v, off);
    __shared__ float s[4];
    if ((tid & 31) == 0) s[tid >> 5] = v;
    __syncthreads();
    if (tid == 0) g_sq[i] = s[0] + s[1] + s[2] + s[3];
}

// ---------------- distance matrix: tiled fp32 "GEMM" ----------------
// 128x128 tile per block, 256 threads, 8x8 micro-tile per thread, BK=16.
__global__ void __launch_bounds__(256) dist_kernel(const float* __restrict__ X) {
    __shared__ float As[16][128];
    __shared__ float Bs[16][128];

    const int bx = blockIdx.x;  // column tile (j)
    const int by = blockIdx.y;  // row tile (i)
    const int tid = threadIdx.x;
    const int tx = tid & 15;
    const int ty = tid >> 4;
    const int rowbase = by * 128;
    const int colbase = bx * 128;

    float acc[8][8];
#pragma unroll
    for (int a = 0; a < 8; a++)
#pragma unroll
        for (int b = 0; b < 8; b++) acc[a][b] = 0.0f;

    for (int k0 = 0; k0 < DIM; k0 += 16) {
#pragma unroll
        for (int r = 0; r < 2; r++) {
            int pos = tid + r * 256;     // 0..511
            int row = pos >> 2;          // 0..127
            int kc  = pos & 3;           // 0..3 (float4 chunk within the 16 k's)
            float4 va = *(const float4*)&X[(size_t)(rowbase + row) * DIM + k0 + kc * 4];
            As[kc * 4 + 0][row] = va.x;
            As[kc * 4 + 1][row] = va.y;
            As[kc * 4 + 2][row] = va.z;
            As[kc * 4 + 3][row] = va.w;
            float4 vb = *(const float4*)&X[(size_t)(colbase + row) * DIM + k0 + kc * 4];
            Bs[kc * 4 + 0][row] = vb.x;
            Bs[kc * 4 + 1][row] = vb.y;
            Bs[kc * 4 + 2][row] = vb.z;
            Bs[kc * 4 + 3][row] = vb.w;
        }
        __syncthreads();
#pragma unroll
        for (int kk = 0; kk < 16; kk++) {
            float ar[8], br[8];
            *(float4*)&ar[0] = *(const float4*)&As[kk][ty * 8];
            *(float4*)&ar[4] = *(const float4*)&As[kk][ty * 8 + 4];
            *(float4*)&br[0] = *(const float4*)&Bs[kk][tx * 8];
            *(float4*)&br[4] = *(const float4*)&Bs[kk][tx * 8 + 4];
#pragma unroll
            for (int a = 0; a < 8; a++)
#pragma unroll
                for (int b = 0; b < 8; b++) acc[a][b] = fmaf(ar[a], br[b], acc[a][b]);
        }
        __syncthreads();
    }

    float sqa[8], sqb[8];
#pragma unroll
    for (int a = 0; a < 8; a++) sqa[a] = g_sq[rowbase + ty * 8 + a];
#pragma unroll
    for (int b = 0; b < 8; b++) sqb[b] = g_sq[colbase + tx * 8 + b];

#pragma unroll
    for (int a = 0; a < 8; a++) {
        int row = rowbase + ty * 8 + a;
        float4 o0, o1;
        o0.x = sqrtf(fmaxf(sqa[a] + sqb[0] - 2.0f * acc[a][0], 1e-12f));
        o0.y = sqrtf(fmaxf(sqa[a] + sqb[1] - 2.0f * acc[a][1], 1e-12f));
        o0.z = sqrtf(fmaxf(sqa[a] + sqb[2] - 2.0f * acc[a][2], 1e-12f));
        o0.w = sqrtf(fmaxf(sqa[a] + sqb[3] - 2.0f * acc[a][3], 1e-12f));
        o1.x = sqrtf(fmaxf(sqa[a] + sqb[4] - 2.0f * acc[a][4], 1e-12f));
        o1.y = sqrtf(fmaxf(sqa[a] + sqb[5] - 2.0f * acc[a][5], 1e-12f));
        o1.z = sqrtf(fmaxf(sqa[a] + sqb[6] - 2.0f * acc[a][6], 1e-12f));
        o1.w = sqrtf(fmaxf(sqa[a] + sqb[7] - 2.0f * acc[a][7], 1e-12f));
        *(float4*)&g_dist[(size_t)row * NPTS + colbase + tx * 8]     = o0;
        *(float4*)&g_dist[(size_t)row * NPTS + colbase + tx * 8 + 4] = o1;
    }
}

// ---------------- per-row: threshold (17th smallest) + masked sums --------
__global__ void __launch_bounds__(256) row_kernel() {
    const int i = blockIdx.x;
    const int tid = threadIdx.x;
    const int lane = tid & 31;
    const int wid = tid >> 5;
    const float INF = __int_as_float(0x7f800000);

    __shared__ float srow[NPTS];           // 32 KB
    __shared__ unsigned char slab[NPTS];   // 8 KB
    __shared__ float rv[8];
    __shared__ int ri[8];
    __shared__ float selv[17];
    __shared__ int seli[17];
    __shared__ float sps[8], sns[8];
    __shared__ int scp[8], scn[8], sfp[8], san[8];

    const float* drow = g_dist + (size_t)i * NPTS;
    for (int j = tid; j < NPTS; j += 256) {
        srow[j] = (j == i) ? INF : drow[j];
        slab[j] = g_lab[j];
    }
    __syncthreads();

    // extract the 17 smallest (0-based index 16 of the sorted row = threshold)
    for (int t = 0; t < 17; t++) {
        float mv = INF;
        int mi = NPTS;
        for (int j = tid; j < NPTS; j += 256) {
            float v = srow[j];
            if (v < mv) { mv = v; mi = j; }
        }
#pragma unroll
        for (int off = 16; off; off >>= 1) {
            float ov = __shfl_down_sync(0xffffffffu, mv, off);
            int   oi = __shfl_down_sync(0xffffffffu, mi, off);
            if (ov < mv || (ov == mv && oi < mi)) { mv = ov; mi = oi; }
        }
        if (lane == 0) { rv[wid] = mv; ri[wid] = mi; }
        __syncthreads();
        if (tid == 0) {
            float bv = rv[0]; int bi = ri[0];
            for (int w = 1; w < 8; w++)
                if (rv[w] < bv || (rv[w] == bv && ri[w] < bi)) { bv = rv[w]; bi = ri[w]; }
            selv[t] = bv; seli[t] = bi;
            srow[bi] = INF;  // remove so next extraction finds the next one
        }
        __syncthreads();
    }
    // restore the extracted values (the sums need them)
    if (tid < 17) srow[seli[tid]] = selv[tid];
    __syncthreads();

    const float thr = selv[16];
    const int myl = slab[i];

    float ps = 0.0f, ns = 0.0f;
    int cp = 0, cn = 0, fp = NPTS, anyneg = 0;
    for (int j = tid; j < NPTS; j += 256) {
        if (j == i) continue;
        float dv = srow[j];
        bool below = dv < thr;
        if (slab[j] == myl) {
            if (j < fp) fp = j;
            if (below) { ps += expf(-dv); cp++; }
        } else {
            anyneg = 1;
            if (below) { ns += expf(-dv); cn++; }
        }
    }
#pragma unroll
    for (int off = 16; off; off >>= 1) {
        ps += __shfl_down_sync(0xffffffffu, ps, off);
        ns += __shfl_down_sync(0xffffffffu, ns, off);
        cp += __shfl_down_sync(0xffffffffu, cp, off);
        cn += __shfl_down_sync(0xffffffffu, cn, off);
        int ofp = __shfl_down_sync(0xffffffffu, fp, off);
        fp = min(fp, ofp);
        anyneg |= __shfl_down_sync(0xffffffffu, anyneg, off);
    }
    if (lane == 0) { sps[wid] = ps; sns[wid] = ns; scp[wid] = cp; scn[wid] = cn; sfp[wid] = fp; san[wid] = anyneg; }
    __syncthreads();
    if (tid == 0) {
        ps = 0; ns = 0; cp = 0; cn = 0; fp = NPTS; anyneg = 0;
        for (int w = 0; w < 8; w++) {
            ps += sps[w]; ns += sns[w]; cp += scp[w]; cn += scn[w];
            fp = min(fp, sfp[w]); anyneg |= san[w];
        }
        bool haspos = (fp < NPTS);
        bool validr = haspos && (anyneg != 0);
        float pos_eff = (cp == 0) ? (haspos ? expf(-srow[fp]) : 1.0f) : ps;
        float loss_i = validr ? logf((pos_eff + ns) / pos_eff) : 0.0f;
        int cpa = (cp == 0) ? 1 : cp;
        g_loss[i] = loss_i;
        g_accv[i] = (validr && cpa > cn) ? 1.0f : 0.0f;
        g_tpv[i]  = validr ? (float)cp : 0.0f;
        g_tnv[i]  = validr ? (float)cn : 0.0f;
    }
}

// ---------------- deterministic final reduction ----------------
__global__ void finalize_kernel(float* __restrict__ out) {
    __shared__ float s0[256], s1[256], s2[256], s3[256];
    int tid = threadIdx.x;
    float a = 0, b = 0, c = 0, d = 0;
    for (int j = tid; j < NPTS; j += 256) {
        a += g_loss[j]; b += g_accv[j]; c += g_tpv[j]; d += g_tnv[j];
    }
    s0[tid] = a; s1[tid] = b; s2[tid] = c; s3[tid] = d;
    __syncthreads();
    for (int off = 128; off; off >>= 1) {
        if (tid < off) {
            s0[tid] += s0[tid + off];
            s1[tid] += s1[tid + off];
            s2[tid] += s2[tid + off];
            s3[tid] += s3[tid + off];
        }
        __syncthreads();
    }
    if (tid == 0) {
        const float inv = 1.0f / (float)NPTS;
        out[0] = s0[0] * inv;  // loss
        out[1] = s1[0] * inv;  // accuracy
        out[2] = s2[0] * inv;  // tp
        out[3] = s3[0] * inv;  // tn
    }
}

extern "C" void kernel_launch(void* const* d_in, const int* in_sizes, int n_in,
                              void* d_out, int out_size) {
    const float* X = (const float*)d_in[0];
    const void* T = d_in[1];
    float* out = (float*)d_out;
    (void)in_sizes; (void)n_in; (void)out_size;

    detect_kernel<<<1, 256>>>((const int*)T);
    conv_kernel<<<(NPTS + 255) / 256, 256>>>(T);
    sq_kernel<<<NPTS, 128>>>(X);
    dim3 grid(NPTS / 128, NPTS / 128);
    dist_kernel<<<grid, 256>>>(X);
    row_kernel<<<NPTS, 256>>>();
    finalize_kernel<<<1, 256>>>(out);
}